// round 4
// baseline (speedup 1.0000x reference)
#include <cuda_runtime.h>
#include <cuda_bf16.h>
#include <math.h>
#include <stdint.h>

#define NN 50000
#define NE 800000
#define HDIM 64
#define NBLK 196   // ceil(50000/256)

#define EI_OFF  3200000LL
#define AL_OFF  4800000LL

// ---------------- scratch (static device globals; no allocation) ----------------
// g_deg is zero at module load and re-zeroed by k_node each call -> every call
// performs identical work (deterministic).
__device__ int   g_src[NE];
__device__ int   g_dst[NE];
__device__ int   g_deg[NN];
__device__ int   g_rowstart[NN + 1];
__device__ int   g_cursor[NN];
__device__ int   g_elist[NE];
__device__ int   g_part[256];
__device__ float g_xl[NN * HDIM];
__device__ float g_xr[NN * HDIM];
__device__ float g_res[NN * HDIM];
__device__ float g_score[NE * 4];   // only used for rare deg>128 fallback

// ---------------- K0: convert (+int64 detect) + degree histogram + ei passthrough ----------------
__global__ void k_convert(const int* __restrict__ ei, float* __restrict__ out, int write_ei) {
    __shared__ int s64;
    if (threadIdx.x == 0) {
        int f = 1;
#pragma unroll
        for (int i = 0; i < 16; i++) f &= (ei[2 * i + 1] == 0);
        s64 = f;
    }
    __syncthreads();
    int is64 = s64;
    int e = blockIdx.x * blockDim.x + threadIdx.x;
    if (e < NE) {
        int s, d;
        if (is64) {
            s = ei[2 * e];
            d = ei[2 * (NE + e)];
        } else {
            s = ei[e];
            d = ei[NE + e];
        }
        g_src[e] = s;
        g_dst[e] = d;
        atomicAdd(&g_deg[d], 1);
        if (write_ei) {
            out[EI_OFF + e]      = (float)s;
            out[EI_OFF + NE + e] = (float)d;
        }
    }
}

// ---------------- K1: fused projections, register-blocked ----------------
__global__ void __launch_bounds__(192) k_proj(
    const float* __restrict__ x,
    const float* __restrict__ Wl, const float* __restrict__ bl,
    const float* __restrict__ Wr, const float* __restrict__ br,
    const float* __restrict__ Wres, const float* __restrict__ bres)
{
    __shared__ __align__(16) float sx[128 * 32];  // [k][r]
    int tid = threadIdx.x;
    int lane = tid & 31;
    int warp = tid >> 5;
    int row0 = blockIdx.x * 32;
    const float4* x4 = reinterpret_cast<const float4*>(x);
    for (int idx = tid; idx < 1024; idx += 192) {
        int r = idx & 31, c4 = idx >> 5;
        int row = row0 + r;
        float4 v = make_float4(0.f, 0.f, 0.f, 0.f);
        if (row < NN) v = x4[row * 32 + c4];
        int k = c4 * 4;
        sx[(k + 0) * 32 + r] = v.x;
        sx[(k + 1) * 32 + r] = v.y;
        sx[(k + 2) * 32 + r] = v.z;
        sx[(k + 3) * 32 + r] = v.w;
    }
    __syncthreads();

    int mat = warp % 3;
    int rh  = warp / 3;
    const float* W = (mat == 0) ? Wl : (mat == 1) ? Wr : Wres;
    const float* B = (mat == 0) ? bl : (mat == 1) ? br : bres;
    float* Out = (mat == 0) ? g_xl : (mat == 1) ? g_xr : g_res;
    int j0 = lane, j1 = lane + 32;

    unsigned long long acc0[8], acc1[8];
#pragma unroll
    for (int i = 0; i < 8; i++) { acc0[i] = 0ULL; acc1[i] = 0ULL; }

#pragma unroll 2
    for (int k = 0; k < 128; k++) {
        float w0 = W[k * 64 + j0];
        float w1 = W[k * 64 + j1];
        unsigned long long wd0, wd1;
        asm("mov.b64 %0, {%1, %2};" : "=l"(wd0) : "f"(w0), "f"(w0));
        asm("mov.b64 %0, {%1, %2};" : "=l"(wd1) : "f"(w1), "f"(w1));
        const unsigned long long* xp =
            reinterpret_cast<const unsigned long long*>(&sx[k * 32 + rh * 16]);
#pragma unroll
        for (int rp = 0; rp < 8; rp++) {
            unsigned long long xv = xp[rp];
            asm("fma.rn.f32x2 %0, %1, %2, %0;" : "+l"(acc0[rp]) : "l"(xv), "l"(wd0));
            asm("fma.rn.f32x2 %0, %1, %2, %0;" : "+l"(acc1[rp]) : "l"(xv), "l"(wd1));
        }
    }

    float b0 = B[j0], b1 = B[j1];
#pragma unroll
    for (int rp = 0; rp < 8; rp++) {
        int row = row0 + rh * 16 + 2 * rp;
        float lo0 = __uint_as_float((unsigned)(acc0[rp] & 0xffffffffULL)) + b0;
        float hi0 = __uint_as_float((unsigned)(acc0[rp] >> 32)) + b0;
        float lo1 = __uint_as_float((unsigned)(acc1[rp] & 0xffffffffULL)) + b1;
        float hi1 = __uint_as_float((unsigned)(acc1[rp] >> 32)) + b1;
        if (row < NN)     { Out[row * 64 + j0] = lo0; Out[row * 64 + j1] = lo1; }
        if (row + 1 < NN) { Out[(row + 1) * 64 + j0] = hi0; Out[(row + 1) * 64 + j1] = hi1; }
    }
}

// ---------------- K2a: per-block partial sums ----------------
__global__ void k_scan1() {
    __shared__ int s[256];
    int t = threadIdx.x;
    int idx = blockIdx.x * 256 + t;
    int v = (idx < NN) ? g_deg[idx] : 0;
    s[t] = v;
    __syncthreads();
#pragma unroll
    for (int off = 128; off > 0; off >>= 1) {
        if (t < off) s[t] += s[t + off];
        __syncthreads();
    }
    if (t == 0) g_part[blockIdx.x] = s[0];
}

// ---------------- K2b: fused partial-scan + local scan ----------------
__global__ void k_scan3() {
    __shared__ int sp[256];
    __shared__ int s[256];
    int t = threadIdx.x;
    int pv = (t < NBLK) ? g_part[t] : 0;
    sp[t] = pv;
    int idx = blockIdx.x * 256 + t;
    int v = (idx < NN) ? g_deg[idx] : 0;
    s[t] = v;
    __syncthreads();
#pragma unroll
    for (int off = 1; off < 256; off <<= 1) {
        int u1 = (t >= off) ? sp[t - off] : 0;
        int u2 = (t >= off) ? s[t - off] : 0;
        __syncthreads();
        sp[t] += u1;
        s[t]  += u2;
        __syncthreads();
    }
    int blk_off = (blockIdx.x == 0) ? 0 : sp[blockIdx.x - 1];
    int excl = s[t] - v + blk_off;
    if (idx < NN) {
        g_rowstart[idx] = excl;
        g_cursor[idx]   = excl;
    }
    if (blockIdx.x == 0 && t == 0) g_rowstart[NN] = sp[NBLK - 1];
}

// ---------------- K3: scatter edges into CSR ----------------
__global__ void k_scatter() {
    int e = blockIdx.x * blockDim.x + threadIdx.x;
    if (e < NE) {
        int d = g_dst[e];
        int pos = atomicAdd(&g_cursor[d], 1);
        g_elist[pos] = e;
    }
}

// ---------------- K4: two-pass per-node kernel ----------------
// Pass A (score): lane = e*4+h (8 edge slots x 4 heads). Each lane computes the
//   full 16-dim GATv2 score for (edge,head) locally -> no per-edge shuffles.
//   Only a 3-shfl max-reduction per 8-edge batch (max needs no rescaling).
// Pass B (aggregate): lane owns output float2 (head = lane>>3). With m fixed,
//   iterations are independent -> unrolled, load-pipelined.
__global__ void __launch_bounds__(128) k_node(
    const float* __restrict__ edge_attr,
    const float* __restrict__ We,
    const float* __restrict__ att,
    const float* __restrict__ bias_out,
    float* __restrict__ out, int do_alpha)
{
    __shared__ int sbuf[4 * 128];
    __shared__ __align__(16) float ssc[4][128 * 4];
    int warp = threadIdx.x >> 5;
    int lane = threadIdx.x & 31;
    int n = blockIdx.x * 4 + warp;
    if (n >= NN) return;
    int* buf = &sbuf[warp * 128];
    float* psc = ssc[warp];

    int start = g_rowstart[n];
    int deg = g_rowstart[n + 1] - start;

    // deterministic: sort this node's edge ids ascending
    if (deg <= 32) {
        int myid = (lane < deg) ? g_elist[start + lane] : 0x7fffffff;
        int rank = 0;
#pragma unroll
        for (int j = 0; j < 32; j++) {
            int o = __shfl_sync(0xffffffffu, myid, j);
            rank += (o < myid);
        }
        if (lane < deg) buf[rank] = myid;
    } else {
        int dd = min(deg, 128);
        for (int i = lane; i < dd; i += 32) {
            int v = g_elist[start + i];
            int rank = 0;
            for (int j = 0; j < dd; j++) rank += (g_elist[start + j] < v);
            buf[rank] = v;
        }
    }
    __syncwarp();
    bool use_buf = (deg <= 128);

    // ---- Pass A: scores + per-head max ----
    int hA = lane & 3;          // this lane's head
    int eslot = lane >> 2;      // this lane's edge slot within a batch of 8
    const float4* xrp  = (const float4*)&g_xr[n * 64 + hA * 16];
    const float4* Wep  = (const float4*)&We[hA * 16];
    const float4* attp = (const float4*)&att[hA * 16];
    float4 xr0 = xrp[0],  xr1 = xrp[1],  xr2 = xrp[2],  xr3 = xrp[3];
    float4 We0 = Wep[0],  We1 = Wep[1],  We2 = Wep[2],  We3 = Wep[3];
    float4 at0 = attp[0], at1 = attp[1], at2 = attp[2], at3 = attp[3];

    const float NEG_INF = __int_as_float(0xff800000);
    float m = NEG_INF;

    for (int base = 0; base < deg; base += 8) {
        int ei = base + eslot;
        bool act = (ei < deg);
        int e = 0;
        if (act) e = use_buf ? buf[ei] : g_elist[start + ei];
        int s = act ? g_src[e] : 0;
        float ea = act ? edge_attr[e] : 0.f;
        const float4* xlp = (const float4*)&g_xl[s * 64 + hA * 16];
        float4 a0 = xlp[0], a1 = xlp[1], a2 = xlp[2], a3 = xlp[3];

        float p0, p1, p2, p3;
        {
#define LRELU(v) (fmaxf((v), 0.f) + 0.2f * fminf((v), 0.f))
            float f;
            f = fmaf(ea, We0.x, a0.x + xr0.x); p0 = at0.x * LRELU(f);
            f = fmaf(ea, We0.y, a0.y + xr0.y); p0 = fmaf(at0.y, LRELU(f), p0);
            f = fmaf(ea, We0.z, a0.z + xr0.z); p0 = fmaf(at0.z, LRELU(f), p0);
            f = fmaf(ea, We0.w, a0.w + xr0.w); p0 = fmaf(at0.w, LRELU(f), p0);
            f = fmaf(ea, We1.x, a1.x + xr1.x); p1 = at1.x * LRELU(f);
            f = fmaf(ea, We1.y, a1.y + xr1.y); p1 = fmaf(at1.y, LRELU(f), p1);
            f = fmaf(ea, We1.z, a1.z + xr1.z); p1 = fmaf(at1.z, LRELU(f), p1);
            f = fmaf(ea, We1.w, a1.w + xr1.w); p1 = fmaf(at1.w, LRELU(f), p1);
            f = fmaf(ea, We2.x, a2.x + xr2.x); p2 = at2.x * LRELU(f);
            f = fmaf(ea, We2.y, a2.y + xr2.y); p2 = fmaf(at2.y, LRELU(f), p2);
            f = fmaf(ea, We2.z, a2.z + xr2.z); p2 = fmaf(at2.z, LRELU(f), p2);
            f = fmaf(ea, We2.w, a2.w + xr2.w); p2 = fmaf(at2.w, LRELU(f), p2);
            f = fmaf(ea, We3.x, a3.x + xr3.x); p3 = at3.x * LRELU(f);
            f = fmaf(ea, We3.y, a3.y + xr3.y); p3 = fmaf(at3.y, LRELU(f), p3);
            f = fmaf(ea, We3.z, a3.z + xr3.z); p3 = fmaf(at3.z, LRELU(f), p3);
            f = fmaf(ea, We3.w, a3.w + xr3.w); p3 = fmaf(at3.w, LRELU(f), p3);
#undef LRELU
        }
        float p = (p0 + p1) + (p2 + p3);
        if (act) {
            if (use_buf) psc[ei * 4 + hA] = p;       // addr = base*4 + lane: conflict-free
            else         g_score[(long long)e * 4 + hA] = p;
        } else {
            p = NEG_INF;
        }
        // max over the 8 edge slots (same head: lanes stride 4)
        p = fmaxf(p, __shfl_xor_sync(0xffffffffu, p, 4));
        p = fmaxf(p, __shfl_xor_sync(0xffffffffu, p, 8));
        p = fmaxf(p, __shfl_xor_sync(0xffffffffu, p, 16));
        m = fmaxf(m, p);
    }
    __syncwarp();

    // ---- Pass B: aggregation (independent iterations) ----
    int hB = lane >> 3;
    float mB = __shfl_sync(0xffffffffu, m, hB);   // lanes 0..3 hold heads 0..3
    float den = 0.f, accx = 0.f, accy = 0.f;

#pragma unroll 4
    for (int i = 0; i < deg; i++) {
        int e = use_buf ? buf[i] : g_elist[start + i];
        float p = use_buf ? psc[i * 4 + hB] : g_score[(long long)e * 4 + hB];
        int s = g_src[e];
        float2 xl2 = *(const float2*)&g_xl[s * 64 + 2 * lane];
        float ex = __expf(p - mB);
        den += ex;
        accx = fmaf(ex, xl2.x, accx);
        accy = fmaf(ex, xl2.y, accy);
    }

    float dfin = den + 1e-16f;
    float2 r2  = *(const float2*)&g_res[n * 64 + 2 * lane];
    float2 bo2 = *(const float2*)&bias_out[2 * lane];
    float ox = accx / dfin + bo2.x + r2.x;
    float oy = accy / dfin + bo2.y + r2.y;
    ox = ox > 0.f ? ox : expm1f(ox);
    oy = oy > 0.f ? oy : expm1f(oy);
    *(float2*)&out[n * 64 + 2 * lane] = make_float2(ox, oy);

    // reset degree counter for next call
    if (lane == 0) g_deg[n] = 0;

    if (do_alpha) {
        float m0 = __shfl_sync(0xffffffffu, m, 0);
        float m1 = __shfl_sync(0xffffffffu, m, 1);
        float m2 = __shfl_sync(0xffffffffu, m, 2);
        float m3 = __shfl_sync(0xffffffffu, m, 3);
        float d0 = __shfl_sync(0xffffffffu, den, 0)  + 1e-16f;
        float d1 = __shfl_sync(0xffffffffu, den, 8)  + 1e-16f;
        float d2 = __shfl_sync(0xffffffffu, den, 16) + 1e-16f;
        float d3 = __shfl_sync(0xffffffffu, den, 24) + 1e-16f;
        for (int i = lane; i < deg; i += 32) {
            int e = use_buf ? buf[i] : g_elist[start + i];
            float4 s4 = use_buf ? *(const float4*)&psc[i * 4]
                                : *(const float4*)&g_score[(long long)e * 4];
            float4 a;
            a.x = __expf(s4.x - m0) / d0;
            a.y = __expf(s4.y - m1) / d1;
            a.z = __expf(s4.z - m2) / d2;
            a.w = __expf(s4.w - m3) / d3;
            *(float4*)&out[AL_OFF + (long long)e * 4] = a;
        }
    }
}

// ---------------- launch ----------------
extern "C" void kernel_launch(void* const* d_in, const int* in_sizes, int n_in,
                              void* d_out, int out_size) {
    const float* x         = (const float*)d_in[0];
    const int*   ei        = (const int*)d_in[1];
    const float* edge_attr = (const float*)d_in[2];
    const float* Wl        = (const float*)d_in[3];
    const float* bl        = (const float*)d_in[4];
    const float* Wr        = (const float*)d_in[5];
    const float* br        = (const float*)d_in[6];
    const float* We        = (const float*)d_in[7];
    const float* att       = (const float*)d_in[8];
    const float* bias_out  = (const float*)d_in[9];
    const float* Wres      = (const float*)d_in[10];
    const float* bres      = (const float*)d_in[11];
    float* out = (float*)d_out;

    int write_ei = (out_size >= 4800000);
    int do_alpha = (out_size >= 8000000);

    static cudaStream_t s2 = 0;
    static cudaEvent_t evA = 0, evB = 0;
    if (!s2) {
        cudaStreamCreateWithFlags(&s2, cudaStreamNonBlocking);
        cudaEventCreateWithFlags(&evA, cudaEventDisableTiming);
        cudaEventCreateWithFlags(&evB, cudaEventDisableTiming);
    }

    // fork: proj runs concurrently with the CSR-build chain
    cudaEventRecord(evA, 0);
    cudaStreamWaitEvent(s2, evA, 0);
    k_proj<<<(NN + 31) / 32, 192, 0, s2>>>(x, Wl, bl, Wr, br, Wres, bres);
    cudaEventRecord(evB, s2);

    k_convert<<<(NE + 255) / 256, 256>>>(ei, out, write_ei);
    k_scan1<<<NBLK, 256>>>();
    k_scan3<<<NBLK, 256>>>();
    k_scatter<<<(NE + 255) / 256, 256>>>();

    // join: node pass needs both the CSR and the projections
    cudaStreamWaitEvent(0, evB, 0);
    k_node<<<(NN + 3) / 4, 128>>>(edge_attr, We, att, bias_out, out, do_alpha);
}